// round 10
// baseline (speedup 1.0000x reference)
#include <cuda_runtime.h>
#include <cuda_bf16.h>
#include <mma.h>
#include <cstdint>

// CycleEmbedding via code-count factorization + tensor-core expand:
//   out = counts @ emb, counts[c,k] = #{e: cycle_e=c, x[atom_e]=k}
// counts exact in bf16 (small ints); emb split hi/lo bf16 for f32-level accuracy.
//
// g_counts zero-initialized at module load; expand_kernel restores every entry
// it reads to zero, preserving the invariant across graph replays.

using namespace nvcuda;

#define HIDDEN 128
#define NUM_CODES 22
#define KPAD 32
#define MAX_SEGMENTS 100000
#define ROWS_PER_BLOCK 128
#define ETHREADS 256

__device__ int g_counts[MAX_SEGMENTS * NUM_CODES];   // 8.8 MB scratch, zero-init

__global__ void __launch_bounds__(256) count_kernel(
    const int* __restrict__ x,
    const int* __restrict__ atom_idx,
    const int* __restrict__ cycle_idx,
    int E8)
{
    int g = blockIdx.x * blockDim.x + threadIdx.x;
    if (g >= E8) return;

    const int4* a4 = reinterpret_cast<const int4*>(atom_idx) + g * 2;
    const int4* c4 = reinterpret_cast<const int4*>(cycle_idx) + g * 2;
    int4 a0 = __ldg(a4);     int4 a1 = __ldg(a4 + 1);
    int4 c0 = __ldg(c4);     int4 c1 = __ldg(c4 + 1);

    int k0 = __ldg(&x[a0.x]); int k1 = __ldg(&x[a0.y]);
    int k2 = __ldg(&x[a0.z]); int k3 = __ldg(&x[a0.w]);
    int k4 = __ldg(&x[a1.x]); int k5 = __ldg(&x[a1.y]);
    int k6 = __ldg(&x[a1.z]); int k7 = __ldg(&x[a1.w]);

    atomicAdd(&g_counts[c0.x * NUM_CODES + k0], 1);
    atomicAdd(&g_counts[c0.y * NUM_CODES + k1], 1);
    atomicAdd(&g_counts[c0.z * NUM_CODES + k2], 1);
    atomicAdd(&g_counts[c0.w * NUM_CODES + k3], 1);
    atomicAdd(&g_counts[c1.x * NUM_CODES + k4], 1);
    atomicAdd(&g_counts[c1.y * NUM_CODES + k5], 1);
    atomicAdd(&g_counts[c1.z * NUM_CODES + k6], 1);
    atomicAdd(&g_counts[c1.w * NUM_CODES + k7], 1);
}

__global__ void __launch_bounds__(256) count_tail_kernel(
    const int* __restrict__ x,
    const int* __restrict__ atom_idx,
    const int* __restrict__ cycle_idx,
    int start, int E)
{
    int e = start + blockIdx.x * blockDim.x + threadIdx.x;
    if (e >= E) return;
    int a = __ldg(&atom_idx[e]);
    int c = __ldg(&cycle_idx[e]);
    int code = __ldg(&x[a]);
    atomicAdd(&g_counts[c * NUM_CODES + code], 1);
}

__global__ void __launch_bounds__(ETHREADS) expand_kernel(
    const float* __restrict__ emb,       // [22, 128]
    float* __restrict__ out,             // [S, 128]
    int S)
{
    __shared__ __nv_bfloat16 sA[ROWS_PER_BLOCK * KPAD];    // 8 KB, counts bf16
    __shared__ __nv_bfloat16 sBhi[KPAD * HIDDEN];          // 8 KB
    __shared__ __nv_bfloat16 sBlo[KPAD * HIDDEN];          // 8 KB
    __shared__ float sBounce[8 * 16 * 16];                 // 8 KB, partial-tile store

    const int tid = threadIdx.x;
    const int row0 = blockIdx.x * ROWS_PER_BLOCK;
    const int nrows = min(ROWS_PER_BLOCK, S - row0);

    // zero A (padding cols / tail rows) and B (padding rows)
    {
        uint32_t* a32 = reinterpret_cast<uint32_t*>(sA);
        for (int i = tid; i < ROWS_PER_BLOCK * KPAD / 2; i += ETHREADS) a32[i] = 0;
        uint32_t* bh = reinterpret_cast<uint32_t*>(sBhi);
        uint32_t* bl = reinterpret_cast<uint32_t*>(sBlo);
        for (int i = tid; i < KPAD * HIDDEN / 2; i += ETHREADS) { bh[i] = 0; bl[i] = 0; }
    }
    __syncthreads();

    // stage counts -> bf16 A; zero-restore global
    {
        const int ncnt = nrows * NUM_CODES;
        int* gbase = &g_counts[row0 * NUM_CODES];
        for (int i = tid; i < ncnt; i += ETHREADS) {
            int v = gbase[i];
            gbase[i] = 0;
            int r = i / NUM_CODES;          // compiler strength-reduces
            int k = i - r * NUM_CODES;
            sA[r * KPAD + k] = __float2bfloat16((float)v);
        }
    }

    // stage emb -> hi/lo bf16 B
    for (int i = tid; i < NUM_CODES * HIDDEN; i += ETHREADS) {
        float v = emb[i];
        __nv_bfloat16 hi = __float2bfloat16(v);
        __nv_bfloat16 lo = __float2bfloat16(v - __bfloat162float(hi));
        int k = i >> 7;                     // /128
        int n = i & 127;
        sBhi[k * HIDDEN + n] = hi;
        sBlo[k * HIDDEN + n] = lo;
    }
    __syncthreads();

    // each warp owns a 16-row tile
    const int warp = tid >> 5;
    const int mrow = row0 + warp * 16;
    if (mrow >= S) return;

    wmma::fragment<wmma::matrix_a, 16, 16, 16, __nv_bfloat16, wmma::row_major> afrag[2];
    wmma::load_matrix_sync(afrag[0], sA + warp * 16 * KPAD, KPAD);
    wmma::load_matrix_sync(afrag[1], sA + warp * 16 * KPAD + 16, KPAD);

    const bool full = (mrow + 16 <= S);
    const int lane = tid & 31;

    #pragma unroll
    for (int n = 0; n < HIDDEN / 16; n++) {
        wmma::fragment<wmma::accumulator, 16, 16, 16, float> acc;
        wmma::fill_fragment(acc, 0.0f);
        #pragma unroll
        for (int ks = 0; ks < 2; ks++) {
            wmma::fragment<wmma::matrix_b, 16, 16, 16, __nv_bfloat16, wmma::row_major> bhi, blo;
            wmma::load_matrix_sync(bhi, sBhi + ks * 16 * HIDDEN + n * 16, HIDDEN);
            wmma::load_matrix_sync(blo, sBlo + ks * 16 * HIDDEN + n * 16, HIDDEN);
            wmma::mma_sync(acc, afrag[ks], bhi, acc);
            wmma::mma_sync(acc, afrag[ks], blo, acc);
        }
        if (full) {
            wmma::store_matrix_sync(out + (size_t)mrow * HIDDEN + n * 16, acc,
                                    HIDDEN, wmma::mem_row_major);
        } else {
            float* bounce = &sBounce[warp * 256];
            wmma::store_matrix_sync(bounce, acc, 16, wmma::mem_row_major);
            __syncwarp();
            int rows_left = S - mrow;       // < 16
            for (int i = lane; i < rows_left * 16; i += 32) {
                int r = i >> 4, cc = i & 15;
                out[(size_t)(mrow + r) * HIDDEN + n * 16 + cc] = bounce[r * 16 + cc];
            }
            __syncwarp();
        }
    }
}

extern "C" void kernel_launch(void* const* d_in, const int* in_sizes, int n_in,
                              void* d_out, int out_size)
{
    const int*   x   = (const int*)d_in[0];
    const int*   a2c = (const int*)d_in[1];
    const float* emb = (const float*)d_in[2];
    float*       out = (float*)d_out;

    const int E = in_sizes[1] / 2;                   // 600000
    const int S = out_size / HIDDEN;                 // 100000
    const int* atom_idx  = a2c;
    const int* cycle_idx = a2c + E;

    // 1) histogram edges into (cycle, code) counts, 8 edges/thread
    int E8 = E >> 3;
    if (E8 > 0)
        count_kernel<<<(E8 + 255) / 256, 256>>>(x, atom_idx, cycle_idx, E8);
    if (E & 7) {
        int start = E8 << 3, n = E - start;
        count_tail_kernel<<<(n + 255) / 256, 256>>>(x, atom_idx, cycle_idx, start, E);
    }

    // 2) expand = counts @ emb on tensor cores (128 rows/block); re-zeros counts
    expand_kernel<<<(S + ROWS_PER_BLOCK - 1) / ROWS_PER_BLOCK, ETHREADS>>>(emb, out, S);
}

// round 11
// speedup vs baseline: 2.5594x; 2.5594x over previous
#include <cuda_runtime.h>
#include <cuda_bf16.h>
#include <cstdint>

// CycleEmbedding via code-count factorization:
//   out[c,:] = sum_k count[c,k] * emb[k,:]
// x: [100000] int32 (0..21), atom_to_cycle: [2, 600000] int32,
// emb_weight: [22,128] f32, out: [100000,128] f32.
//
// g_counts zero-initialized at module load; expand_kernel restores every entry
// it reads to zero, preserving the all-zero invariant across graph replays.

#define HIDDEN 128
#define NUM_CODES 22
#define MAX_SEGMENTS 100000
#define ROWS_PER_WARP 4
#define EWARPS 8
#define ETHREADS (EWARPS * 32)
#define ROWS_PER_BLOCK (EWARPS * ROWS_PER_WARP)   // 32

__device__ int g_counts[MAX_SEGMENTS * NUM_CODES];   // 8.8 MB scratch, zero-init

__global__ void __launch_bounds__(256) count_kernel(
    const int* __restrict__ x,
    const int* __restrict__ atom_idx,
    const int* __restrict__ cycle_idx,
    int E8)
{
    int g = blockIdx.x * blockDim.x + threadIdx.x;
    if (g >= E8) return;

    const int4* a4 = reinterpret_cast<const int4*>(atom_idx) + g * 2;
    const int4* c4 = reinterpret_cast<const int4*>(cycle_idx) + g * 2;
    int4 a0 = __ldg(a4);     int4 a1 = __ldg(a4 + 1);
    int4 c0 = __ldg(c4);     int4 c1 = __ldg(c4 + 1);

    int k0 = __ldg(&x[a0.x]); int k1 = __ldg(&x[a0.y]);
    int k2 = __ldg(&x[a0.z]); int k3 = __ldg(&x[a0.w]);
    int k4 = __ldg(&x[a1.x]); int k5 = __ldg(&x[a1.y]);
    int k6 = __ldg(&x[a1.z]); int k7 = __ldg(&x[a1.w]);

    atomicAdd(&g_counts[c0.x * NUM_CODES + k0], 1);
    atomicAdd(&g_counts[c0.y * NUM_CODES + k1], 1);
    atomicAdd(&g_counts[c0.z * NUM_CODES + k2], 1);
    atomicAdd(&g_counts[c0.w * NUM_CODES + k3], 1);
    atomicAdd(&g_counts[c1.x * NUM_CODES + k4], 1);
    atomicAdd(&g_counts[c1.y * NUM_CODES + k5], 1);
    atomicAdd(&g_counts[c1.z * NUM_CODES + k6], 1);
    atomicAdd(&g_counts[c1.w * NUM_CODES + k7], 1);
}

__global__ void __launch_bounds__(256) count_tail_kernel(
    const int* __restrict__ x,
    const int* __restrict__ atom_idx,
    const int* __restrict__ cycle_idx,
    int start, int E)
{
    int e = start + blockIdx.x * blockDim.x + threadIdx.x;
    if (e >= E) return;
    int a = __ldg(&atom_idx[e]);
    int c = __ldg(&cycle_idx[e]);
    int code = __ldg(&x[a]);
    atomicAdd(&g_counts[c * NUM_CODES + code], 1);
}

__global__ void __launch_bounds__(ETHREADS) expand_kernel(
    const float* __restrict__ emb,       // [22, 128]
    float* __restrict__ out,             // [S, 128]
    int S)
{
    __shared__ float s_emb[NUM_CODES * HIDDEN];           // 11 KB

    // vectorized emb staging: 2816 floats = 704 float4
    {
        const float4* e4 = reinterpret_cast<const float4*>(emb);
        float4* s4 = reinterpret_cast<float4*>(s_emb);
        for (int i = threadIdx.x; i < NUM_CODES * HIDDEN / 4; i += ETHREADS)
            s4[i] = __ldg(e4 + i);
    }

    const int lane = threadIdx.x & 31;
    const int warp = threadIdx.x >> 5;                    // 0..7
    const int row_base = blockIdx.x * ROWS_PER_BLOCK + warp * ROWS_PER_WARP;
    const unsigned FULL = 0xffffffffu;

    // ---- load counts for 4 rows (independent 88B loads) ----
    int cnt[ROWS_PER_WARP];
    #pragma unroll
    for (int r = 0; r < ROWS_PER_WARP; r++) {
        int row = row_base + r;
        cnt[r] = (lane < NUM_CODES && row < S)
                   ? __ldg(&g_counts[row * NUM_CODES + lane]) : 0;
    }

    // ---- build packed term lists in registers ----
    // lane l < nt_r holds pack_r = ((code*512) << 16) | count (count fits 16b here)
    int pack[ROWS_PER_WARP];
    int m = 0;
    #pragma unroll
    for (int r = 0; r < ROWS_PER_WARP; r++) {
        unsigned mask = __ballot_sync(FULL, cnt[r] != 0);
        int nt = __popc(mask);
        m = max(m, nt);
        int code = (lane < nt) ? (__fns(mask, 0, lane + 1)) : 0;
        int c2 = __shfl_sync(FULL, cnt[r], code);
        pack[r] = (lane < nt) ? (((code * (HIDDEN * 4)) << 16) | c2) : 0;
        // zero-restore
        int row = row_base + r;
        if (lane < NUM_CODES && row < S)
            g_counts[row * NUM_CODES + lane] = 0;
    }
    __syncthreads();   // s_emb ready

    // ---- hot loop: shfl-indexed terms, all chains independent ----
    const char* const embb = (const char*)s_emb;
    const uint32_t lane_off = (uint32_t)lane << 4;

    float4 acc0 = make_float4(0.f,0.f,0.f,0.f), acc1 = acc0, acc2 = acc0, acc3 = acc0;

    for (int j = 0; j < m; j++) {
        int p0 = __shfl_sync(FULL, pack[0], j);
        int p1 = __shfl_sync(FULL, pack[1], j);
        int p2 = __shfl_sync(FULL, pack[2], j);
        int p3 = __shfl_sync(FULL, pack[3], j);
        float f0 = (float)(p0 & 0xFFFF);
        float f1 = (float)(p1 & 0xFFFF);
        float f2 = (float)(p2 & 0xFFFF);
        float f3 = (float)(p3 & 0xFFFF);
        float4 e0 = *reinterpret_cast<const float4*>(embb + ((uint32_t)p0 >> 16) + lane_off);
        float4 e1 = *reinterpret_cast<const float4*>(embb + ((uint32_t)p1 >> 16) + lane_off);
        float4 e2 = *reinterpret_cast<const float4*>(embb + ((uint32_t)p2 >> 16) + lane_off);
        float4 e3 = *reinterpret_cast<const float4*>(embb + ((uint32_t)p3 >> 16) + lane_off);
        acc0.x += f0*e0.x; acc0.y += f0*e0.y; acc0.z += f0*e0.z; acc0.w += f0*e0.w;
        acc1.x += f1*e1.x; acc1.y += f1*e1.y; acc1.z += f1*e1.z; acc1.w += f1*e1.w;
        acc2.x += f2*e2.x; acc2.y += f2*e2.y; acc2.z += f2*e2.z; acc2.w += f2*e2.w;
        acc3.x += f3*e3.x; acc3.y += f3*e3.y; acc3.z += f3*e3.z; acc3.w += f3*e3.w;
    }

    float4* out4 = reinterpret_cast<float4*>(out);
    if (row_base + 0 < S) out4[(size_t)(row_base + 0) * 32 + lane] = acc0;
    if (row_base + 1 < S) out4[(size_t)(row_base + 1) * 32 + lane] = acc1;
    if (row_base + 2 < S) out4[(size_t)(row_base + 2) * 32 + lane] = acc2;
    if (row_base + 3 < S) out4[(size_t)(row_base + 3) * 32 + lane] = acc3;
}

extern "C" void kernel_launch(void* const* d_in, const int* in_sizes, int n_in,
                              void* d_out, int out_size)
{
    const int*   x   = (const int*)d_in[0];
    const int*   a2c = (const int*)d_in[1];
    const float* emb = (const float*)d_in[2];
    float*       out = (float*)d_out;

    const int E = in_sizes[1] / 2;                   // 600000
    const int S = out_size / HIDDEN;                 // 100000
    const int* atom_idx  = a2c;
    const int* cycle_idx = a2c + E;

    // 1) histogram edges into (cycle, code) counts, 8 edges/thread
    int E8 = E >> 3;
    if (E8 > 0)
        count_kernel<<<(E8 + 255) / 256, 256>>>(x, atom_idx, cycle_idx, E8);
    if (E & 7) {
        int start = E8 << 3, n = E - start;
        count_tail_kernel<<<(n + 255) / 256, 256>>>(x, atom_idx, cycle_idx, start, E);
    }

    // 2) expand counts -> output rows (32 rows/block); also re-zeros counts
    expand_kernel<<<(S + ROWS_PER_BLOCK - 1) / ROWS_PER_BLOCK, ETHREADS>>>(emb, out, S);
}

// round 12
// speedup vs baseline: 2.5621x; 1.0010x over previous
#include <cuda_runtime.h>
#include <cuda_bf16.h>
#include <cstdint>

// CycleEmbedding via code-count factorization:
//   out[c,:] = sum_k count[c,k] * emb[k,:]
// x: [100000] int32 (0..21), atom_to_cycle: [2, 600000] int32,
// emb_weight: [22,128] f32, out: [100000,128] f32.
//
// g_counts zero-initialized at module load; expand_kernel restores every entry
// it reads to zero, preserving the all-zero invariant across graph replays.
//
// Hot-loop encoding: term pack = (code*512) << 16 | bf16bits(count).
// Counts are small integers (Poisson ~0.27 mean per cell, <<256) so bf16 is
// exact; count recovery is a single shift (reinterpret as f32).

#define HIDDEN 128
#define NUM_CODES 22
#define MAX_SEGMENTS 100000
#define ROWS_PER_WARP 4
#define EWARPS 8
#define ETHREADS (EWARPS * 32)
#define ROWS_PER_BLOCK (EWARPS * ROWS_PER_WARP)   // 32

__device__ int g_counts[MAX_SEGMENTS * NUM_CODES];   // 8.8 MB scratch, zero-init

__global__ void __launch_bounds__(256) count_kernel(
    const int* __restrict__ x,
    const int* __restrict__ atom_idx,
    const int* __restrict__ cycle_idx,
    int E8)
{
    int g = blockIdx.x * blockDim.x + threadIdx.x;
    if (g >= E8) return;

    const int4* a4 = reinterpret_cast<const int4*>(atom_idx) + g * 2;
    const int4* c4 = reinterpret_cast<const int4*>(cycle_idx) + g * 2;
    int4 a0 = __ldg(a4);     int4 a1 = __ldg(a4 + 1);
    int4 c0 = __ldg(c4);     int4 c1 = __ldg(c4 + 1);

    int k0 = __ldg(&x[a0.x]); int k1 = __ldg(&x[a0.y]);
    int k2 = __ldg(&x[a0.z]); int k3 = __ldg(&x[a0.w]);
    int k4 = __ldg(&x[a1.x]); int k5 = __ldg(&x[a1.y]);
    int k6 = __ldg(&x[a1.z]); int k7 = __ldg(&x[a1.w]);

    atomicAdd(&g_counts[c0.x * NUM_CODES + k0], 1);
    atomicAdd(&g_counts[c0.y * NUM_CODES + k1], 1);
    atomicAdd(&g_counts[c0.z * NUM_CODES + k2], 1);
    atomicAdd(&g_counts[c0.w * NUM_CODES + k3], 1);
    atomicAdd(&g_counts[c1.x * NUM_CODES + k4], 1);
    atomicAdd(&g_counts[c1.y * NUM_CODES + k5], 1);
    atomicAdd(&g_counts[c1.z * NUM_CODES + k6], 1);
    atomicAdd(&g_counts[c1.w * NUM_CODES + k7], 1);
}

__global__ void __launch_bounds__(256) count_tail_kernel(
    const int* __restrict__ x,
    const int* __restrict__ atom_idx,
    const int* __restrict__ cycle_idx,
    int start, int E)
{
    int e = start + blockIdx.x * blockDim.x + threadIdx.x;
    if (e >= E) return;
    int a = __ldg(&atom_idx[e]);
    int c = __ldg(&cycle_idx[e]);
    int code = __ldg(&x[a]);
    atomicAdd(&g_counts[c * NUM_CODES + code], 1);
}

__device__ __forceinline__ void fma2(unsigned long long& acc,
                                     unsigned long long e,
                                     unsigned long long f)
{
    asm("fma.rn.f32x2 %0, %1, %2, %0;" : "+l"(acc) : "l"(e), "l"(f));
}

__global__ void __launch_bounds__(ETHREADS) expand_kernel(
    const float* __restrict__ emb,       // [22, 128]
    float* __restrict__ out,             // [S, 128]
    int S)
{
    __shared__ float s_emb[NUM_CODES * HIDDEN];           // 11 KB

    {
        const float4* e4 = reinterpret_cast<const float4*>(emb);
        float4* s4 = reinterpret_cast<float4*>(s_emb);
        for (int i = threadIdx.x; i < NUM_CODES * HIDDEN / 4; i += ETHREADS)
            s4[i] = __ldg(e4 + i);
    }

    const int lane = threadIdx.x & 31;
    const int warp = threadIdx.x >> 5;                    // 0..7
    const int row_base = blockIdx.x * ROWS_PER_BLOCK + warp * ROWS_PER_WARP;
    const unsigned FULL = 0xffffffffu;

    // ---- load counts for 4 rows (independent 88B loads) ----
    int cnt[ROWS_PER_WARP];
    #pragma unroll
    for (int r = 0; r < ROWS_PER_WARP; r++) {
        int row = row_base + r;
        cnt[r] = (lane < NUM_CODES && row < S)
                   ? __ldg(&g_counts[row * NUM_CODES + lane]) : 0;
    }

    // ---- build packed term lists in registers ----
    // lane l < nt_r: pack_r = ((code*512) << 16) | bf16bits((float)count)
    int pack[ROWS_PER_WARP];
    int m = 0;
    #pragma unroll
    for (int r = 0; r < ROWS_PER_WARP; r++) {
        unsigned mask = __ballot_sync(FULL, cnt[r] != 0);
        int nt = __popc(mask);
        m = max(m, nt);
        int code = (lane < nt) ? (__fns(mask, 0, lane + 1)) : 0;
        int c2 = __shfl_sync(FULL, cnt[r], code);
        unsigned bf = __float_as_uint((float)c2) >> 16;   // exact for small ints
        pack[r] = (lane < nt) ? (((code * (HIDDEN * 4)) << 16) | (int)bf) : 0;
        // zero-restore
        int row = row_base + r;
        if (lane < NUM_CODES && row < S)
            g_counts[row * NUM_CODES + lane] = 0;
    }
    __syncthreads();   // s_emb ready

    // ---- hot loop: shfl-indexed terms, f32x2 FFMA, all chains independent ----
    const char* const embb = (const char*)s_emb;
    const uint32_t lane_off = (uint32_t)lane << 4;

    unsigned long long A0a = 0, A0b = 0, A1a = 0, A1b = 0,
                       A2a = 0, A2b = 0, A3a = 0, A3b = 0;

    for (int j = 0; j < m; j++) {
        int p0 = __shfl_sync(FULL, pack[0], j);
        int p1 = __shfl_sync(FULL, pack[1], j);
        int p2 = __shfl_sync(FULL, pack[2], j);
        int p3 = __shfl_sync(FULL, pack[3], j);

        unsigned f0 = (unsigned)p0 << 16;   // bf16 count -> f32 bits
        unsigned f1 = (unsigned)p1 << 16;
        unsigned f2 = (unsigned)p2 << 16;
        unsigned f3 = (unsigned)p3 << 16;
        unsigned long long F0, F1, F2, F3;  // {f,f}
        asm("mov.b64 %0, {%1, %1};" : "=l"(F0) : "r"(f0));
        asm("mov.b64 %0, {%1, %1};" : "=l"(F1) : "r"(f1));
        asm("mov.b64 %0, {%1, %1};" : "=l"(F2) : "r"(f2));
        asm("mov.b64 %0, {%1, %1};" : "=l"(F3) : "r"(f3));

        ulonglong2 e0 = *reinterpret_cast<const ulonglong2*>(embb + ((uint32_t)p0 >> 16) + lane_off);
        ulonglong2 e1 = *reinterpret_cast<const ulonglong2*>(embb + ((uint32_t)p1 >> 16) + lane_off);
        ulonglong2 e2 = *reinterpret_cast<const ulonglong2*>(embb + ((uint32_t)p2 >> 16) + lane_off);
        ulonglong2 e3 = *reinterpret_cast<const ulonglong2*>(embb + ((uint32_t)p3 >> 16) + lane_off);

        fma2(A0a, e0.x, F0); fma2(A0b, e0.y, F0);
        fma2(A1a, e1.x, F1); fma2(A1b, e1.y, F1);
        fma2(A2a, e2.x, F2); fma2(A2b, e2.y, F2);
        fma2(A3a, e3.x, F3); fma2(A3b, e3.y, F3);
    }

    ulonglong2* out2 = reinterpret_cast<ulonglong2*>(out);
    if (row_base + 0 < S) out2[(size_t)(row_base + 0) * 32 + lane] = make_ulonglong2(A0a, A0b);
    if (row_base + 1 < S) out2[(size_t)(row_base + 1) * 32 + lane] = make_ulonglong2(A1a, A1b);
    if (row_base + 2 < S) out2[(size_t)(row_base + 2) * 32 + lane] = make_ulonglong2(A2a, A2b);
    if (row_base + 3 < S) out2[(size_t)(row_base + 3) * 32 + lane] = make_ulonglong2(A3a, A3b);
}

extern "C" void kernel_launch(void* const* d_in, const int* in_sizes, int n_in,
                              void* d_out, int out_size)
{
    const int*   x   = (const int*)d_in[0];
    const int*   a2c = (const int*)d_in[1];
    const float* emb = (const float*)d_in[2];
    float*       out = (float*)d_out;

    const int E = in_sizes[1] / 2;                   // 600000
    const int S = out_size / HIDDEN;                 // 100000
    const int* atom_idx  = a2c;
    const int* cycle_idx = a2c + E;

    // 1) histogram edges into (cycle, code) counts, 8 edges/thread
    int E8 = E >> 3;
    if (E8 > 0)
        count_kernel<<<(E8 + 255) / 256, 256>>>(x, atom_idx, cycle_idx, E8);
    if (E & 7) {
        int start = E8 << 3, n = E - start;
        count_tail_kernel<<<(n + 255) / 256, 256>>>(x, atom_idx, cycle_idx, start, E);
    }

    // 2) expand counts -> output rows (32 rows/block); also re-zeros counts
    expand_kernel<<<(S + ROWS_PER_BLOCK - 1) / ROWS_PER_BLOCK, ETHREADS>>>(emb, out, S);
}